// round 8
// baseline (speedup 1.0000x reference)
#include <cuda_runtime.h>
#include <cstdint>

// CC3DTrack: per-track Kalman update + embedding EMA, fused into ONE kernel.
// Grid interleaves roles: every 17th CTA (x % 17 == 16) runs the KF path for
// 256 tracks; the other 16/17 run the embedding-EMA stream (1024 float4 each,
// 4 independent float4 pairs per thread for deep MLP). This overlaps the
// latency-bound KF work with the DRAM-bound embedding stream instead of
// running them serially.
//
// Output (concatenated f32): boxes(12N) | means(10N) | covs(100N) | vel(7N) | emb(256N) | acc(1N)

#define MD 7
#define SD 10
#define KF_TRACKS_PER_CTA 256
#define EMB_V4_PER_CTA 1024   // 256 threads * 4 float4

__global__ __launch_bounds__(256)
void fused_kernel(const float* __restrict__ boxes,
                  const float* __restrict__ obs,
                  const float* __restrict__ prev_b7,
                  const float* __restrict__ prev_mean,
                  const float* __restrict__ prev_cov,
                  const float* __restrict__ prev_vel,
                  const float4* __restrict__ prev_emb,
                  const float4* __restrict__ emb,
                  const int*   __restrict__ acc_frames,
                  const int*   __restrict__ frame_gap,
                  const int*   __restrict__ matched,
                  const int*   __restrict__ fps_p,
                  float* __restrict__ out,
                  int N, int kf_blocks, int total4)
{
    const int x = blockIdx.x;
    const int tid = threadIdx.x;
    const bool is_kf = (x % 17) == 16;

    if (!is_kf) {
        // ---------------- embedding EMA path ----------------
        int kf_before = (x >= 16) ? ((x - 16) / 17 + 1) : 0;
        int emb_idx = x - kf_before;
        float4* emb_out = reinterpret_cast<float4*>(out + (size_t)N * 129);

        long long base = (long long)emb_idx * EMB_V4_PER_CTA + tid;
        // 4 independent elements, stride 256 (coalesced within each group)
        #pragma unroll
        for (int g = 0; g < 4; g++) {
            long long idx = base + g * 256;
            if (idx < total4) {
                bool mt = matched[idx >> 6] != 0;
                float4 ev = __ldcs(emb + idx);
                float4 r;
                if (mt) {
                    float4 pv = __ldcs(prev_emb + idx);
                    r.x = 0.2f * pv.x + 0.8f * ev.x;
                    r.y = 0.2f * pv.y + 0.8f * ev.y;
                    r.z = 0.2f * pv.z + 0.8f * ev.z;
                    r.w = 0.2f * pv.w + 0.8f * ev.w;
                } else {
                    r = ev;
                }
                __stcs(emb_out + idx, r);
            }
        }
        return;
    }

    // ---------------- KF path (one thread per track; R2-proven body) ----------------
    int kf_idx = x / 17;
    if (kf_idx >= kf_blocks) return;
    int n = kf_idx * KF_TRACKS_PER_CTA + tid;
    if (n >= N) return;

    // fps may be serialized as int32 or float32; sniff the bits.
    int fbits = fps_p[0];
    float fps = ((unsigned)fbits < 1000000u) ? (float)fbits : __int_as_float(fbits);

    const float* C = prev_cov + (size_t)n * 100;
    const bool mt = matched[n] != 0;

    // ---- Cholesky of S = C[0:7,0:7] + I (SPD by construction) ----
    float L[MD][MD];
    float dinv[MD];
    #pragma unroll
    for (int i = 0; i < MD; i++) {
        #pragma unroll
        for (int j = 0; j <= i; j++) {
            float s = C[i * SD + j] + (i == j ? 1.0f : 0.0f);
            #pragma unroll
            for (int k = 0; k < j; k++) s -= L[i][k] * L[j][k];
            if (j == i) {
                float d = sqrtf(s);
                L[i][i] = d;
                dinv[i] = 1.0f / d;
            } else {
                L[i][j] = s * dinv[j];
            }
        }
    }

    // ---- W[j][:] = L^{-1} * C[j,0:7]^T;  cov_u = C - W W^T, K innov = W^T (L^{-1} innov)
    float W[SD][MD];
    #pragma unroll
    for (int j = 0; j < SD; j++) {
        float p[MD];
        #pragma unroll
        for (int k = 0; k < MD; k++) p[k] = C[j * SD + k];
        #pragma unroll
        for (int k = 0; k < MD; k++) {
            float s = p[k];
            #pragma unroll
            for (int m = 0; m < k; m++) s -= L[k][m] * W[j][m];
            W[j][k] = s * dinv[k];
        }
    }

    // ---- mean update ----
    float m[SD], o7[MD];
    {
        const float* pm = prev_mean + (size_t)n * SD;
        #pragma unroll
        for (int j = 0; j < SD; j++) m[j] = pm[j];
        const float* po = obs + (size_t)n * MD;
        #pragma unroll
        for (int k = 0; k < MD; k++) o7[k] = po[k];
    }
    float u[MD];
    #pragma unroll
    for (int k = 0; k < MD; k++) {
        float s = o7[k] - m[k];
        #pragma unroll
        for (int mm = 0; mm < k; mm++) s -= L[k][mm] * u[mm];
        u[k] = s * dinv[k];
    }
    float mu[SD];
    #pragma unroll
    for (int j = 0; j < SD; j++) {
        float d = 0.0f;
        #pragma unroll
        for (int k = 0; k < MD; k++) d += W[j][k] * u[k];
        mu[j] = m[j] + d;
    }

    // ---- new_means ----
    {
        float* om = out + (size_t)N * 12 + (size_t)n * SD;
        float r[SD];
        #pragma unroll
        for (int j = 0; j < MD; j++) r[j] = mt ? mu[j] : o7[j];
        #pragma unroll
        for (int j = MD; j < SD; j++) r[j] = mt ? mu[j] : 0.0f;
        float2* om2 = reinterpret_cast<float2*>(om);
        #pragma unroll
        for (int q = 0; q < 5; q++) om2[q] = make_float2(r[2 * q], r[2 * q + 1]);
    }

    // ---- new_covs: cov_u = C - W W^T (or init diag), 25x float4 stream ----
    {
        const float4* C4 = reinterpret_cast<const float4*>(C);
        float4* oc4 = reinterpret_cast<float4*>(out + (size_t)N * 22 + (size_t)n * 100);
        #pragma unroll
        for (int q4 = 0; q4 < 25; q4++) {
            float4 cv = C4[q4];
            float r[4];
            #pragma unroll
            for (int t = 0; t < 4; t++) {
                int q = q4 * 4 + t;
                int i = q / SD, j = q % SD;
                float c = (t == 0) ? cv.x : (t == 1) ? cv.y : (t == 2) ? cv.z : cv.w;
                float d = 0.0f;
                #pragma unroll
                for (int k = 0; k < MD; k++) d += W[i][k] * W[j][k];
                float cu = c - d;
                float ci = (i == j) ? ((i < MD) ? 10.0f : 10000.0f) : 0.0f;
                r[t] = mt ? cu : ci;
            }
            __stcs(oc4 + q4, make_float4(r[0], r[1], r[2], r[3]));
        }
    }

    // ---- new_boxes_3d ----
    {
        const float4* B4 = reinterpret_cast<const float4*>(boxes + (size_t)n * 12);
        float4 b0 = B4[0], b1 = B4[1], b2 = B4[2];
        float b[12] = {b0.x, b0.y, b0.z, b0.w, b1.x, b1.y, b1.z, b1.w,
                       b2.x, b2.y, b2.z, b2.w};
        float r[12];
        #pragma unroll
        for (int j = 0; j < 6; j++) r[j] = mt ? mu[j] : b[j];
        r[6] = b[6];
        r[7] = b[7];
        r[8] = mt ? mu[6] : b[8];
        #pragma unroll
        for (int j = 0; j < 3; j++) r[9 + j] = mt ? (mu[MD + j] * fps) : b[9 + j];
        float4* ob4 = reinterpret_cast<float4*>(out + (size_t)n * 12);
        ob4[0] = make_float4(r[0], r[1], r[2], r[3]);
        ob4[1] = make_float4(r[4], r[5], r[6], r[7]);
        ob4[2] = make_float4(r[8], r[9], r[10], r[11]);
    }

    // ---- velocities + acc_frames ----
    {
        float gap = (float)frame_gap[n];
        float acc = (float)acc_frames[n];
        const float* pb = prev_b7 + (size_t)n * MD;
        const float* pv = prev_vel + (size_t)n * MD;
        float* ov = out + (size_t)N * 122 + (size_t)n * MD;
        float inv_gap = 1.0f / gap;
        float inv_acc1 = 1.0f / (acc + 1.0f);
        #pragma unroll
        for (int k = 0; k < MD; k++) {
            float vobs = (mu[k] - pb[k]) * inv_gap;
            float vm = (pv[k] * acc + vobs) * inv_acc1;
            ov[k] = mt ? vm : 0.0f;
        }
        out[(size_t)N * 385 + n] = mt ? (acc + 1.0f) : 0.0f;
    }
}

extern "C" void kernel_launch(void* const* d_in, const int* in_sizes, int n_in,
                              void* d_out, int out_size)
{
    const float* boxes   = (const float*)d_in[0];
    const float* obs     = (const float*)d_in[1];
    const float* prev_b7 = (const float*)d_in[2];
    const float* prev_m  = (const float*)d_in[3];
    const float* prev_c  = (const float*)d_in[4];
    const float* prev_v  = (const float*)d_in[5];
    const float* prev_e  = (const float*)d_in[6];
    const float* emb     = (const float*)d_in[7];
    const int*   acc     = (const int*)d_in[8];
    const int*   gap     = (const int*)d_in[9];
    const int*   matched = (const int*)d_in[10];
    const int*   fps     = (const int*)d_in[11];
    float* out = (float*)d_out;

    int N = in_sizes[8];  // acc_frames element count == N
    int total4 = N * 64;  // N*256 floats / 4

    int kf_blocks  = (N + KF_TRACKS_PER_CTA - 1) / KF_TRACKS_PER_CTA;
    int emb_blocks = (total4 + EMB_V4_PER_CTA - 1) / EMB_V4_PER_CTA;

    // Interleave: every 17th CTA is a KF CTA. Need enough slots for both roles.
    long long need_for_kf  = 17LL * kf_blocks;              // kf ctas at x=17m+16
    long long need_for_emb = emb_blocks + (emb_blocks + 15) / 16;  // emb slots skipping kf slots
    long long grid = need_for_kf > need_for_emb ? need_for_kf : need_for_emb;

    fused_kernel<<<(int)grid, 256>>>(boxes, obs, prev_b7, prev_m, prev_c, prev_v,
                                     (const float4*)prev_e, (const float4*)emb,
                                     acc, gap, matched, fps, out,
                                     N, kf_blocks, total4);
}

// round 10
// speedup vs baseline: 1.8409x; 1.8409x over previous
#include <cuda_runtime.h>
#include <cstdint>

// CC3DTrack: per-track Kalman update + embedding EMA.
// R2-proven two-kernel structure. emb_kernel is launched FIRST so that the
// ncu capture window (-s 5 -c 1 => 6th launch) lands on kf_kernel, which has
// never been profiled. Order does not affect correctness or total time (the
// graph serializes both).
//
// Output (concatenated f32): boxes(12N) | means(10N) | covs(100N) | vel(7N) | emb(256N) | acc(1N)

#define MD 7
#define SD 10

__global__ __launch_bounds__(128)
void kf_kernel(const float* __restrict__ boxes,
               const float* __restrict__ obs,
               const float* __restrict__ prev_b7,
               const float* __restrict__ prev_mean,
               const float* __restrict__ prev_cov,
               const float* __restrict__ prev_vel,
               const int*   __restrict__ acc_frames,
               const int*   __restrict__ frame_gap,
               const int*   __restrict__ matched,
               const int*   __restrict__ fps_p,
               float* __restrict__ out, int N)
{
    int n = blockIdx.x * blockDim.x + threadIdx.x;
    if (n >= N) return;

    // fps may be serialized as int32 or float32; sniff the bits.
    int fbits = fps_p[0];
    float fps = ((unsigned)fbits < 1000000u) ? (float)fbits : __int_as_float(fbits);

    const float* C = prev_cov + (size_t)n * 100;
    const bool mt = matched[n] != 0;

    // ---- Cholesky of S = C[0:7,0:7] + I (SPD by construction) ----
    float L[MD][MD];
    float dinv[MD];
    #pragma unroll
    for (int i = 0; i < MD; i++) {
        #pragma unroll
        for (int j = 0; j <= i; j++) {
            float s = __ldcs(C + i * SD + j) + (i == j ? 1.0f : 0.0f);
            #pragma unroll
            for (int k = 0; k < j; k++) s -= L[i][k] * L[j][k];
            if (j == i) {
                float d = sqrtf(s);
                L[i][i] = d;
                dinv[i] = 1.0f / d;
            } else {
                L[i][j] = s * dinv[j];
            }
        }
    }

    // ---- W[j][:] = L^{-1} * C[j,0:7]^T ----
    // Then: (K S K^T)[i][j] = W_i . W_j   and   (K innov)[j] = W_j . (L^{-1} innov)
    float W[SD][MD];
    #pragma unroll
    for (int j = 0; j < SD; j++) {
        float p[MD];
        #pragma unroll
        for (int k = 0; k < MD; k++) p[k] = __ldcs(C + j * SD + k);
        #pragma unroll
        for (int k = 0; k < MD; k++) {
            float s = p[k];
            #pragma unroll
            for (int m = 0; m < k; m++) s -= L[k][m] * W[j][m];
            W[j][k] = s * dinv[k];
        }
    }

    // ---- mean update ----
    float m[SD], o7[MD];
    {
        const float* pm = prev_mean + (size_t)n * SD;
        #pragma unroll
        for (int j = 0; j < SD; j++) m[j] = pm[j];
        const float* po = obs + (size_t)n * MD;
        #pragma unroll
        for (int k = 0; k < MD; k++) o7[k] = po[k];
    }
    float u[MD];
    #pragma unroll
    for (int k = 0; k < MD; k++) {
        float s = o7[k] - m[k];
        #pragma unroll
        for (int mm = 0; mm < k; mm++) s -= L[k][mm] * u[mm];
        u[k] = s * dinv[k];
    }
    float mu[SD];
    #pragma unroll
    for (int j = 0; j < SD; j++) {
        float d = 0.0f;
        #pragma unroll
        for (int k = 0; k < MD; k++) d += W[j][k] * u[k];
        mu[j] = m[j] + d;
    }

    // ---- new_means ----
    {
        float* om = out + (size_t)N * 12 + (size_t)n * SD;
        float r[SD];
        #pragma unroll
        for (int j = 0; j < MD; j++) r[j] = mt ? mu[j] : o7[j];
        #pragma unroll
        for (int j = MD; j < SD; j++) r[j] = mt ? mu[j] : 0.0f;
        float2* om2 = reinterpret_cast<float2*>(om);
        #pragma unroll
        for (int q = 0; q < 5; q++) om2[q] = make_float2(r[2 * q], r[2 * q + 1]);
    }

    // ---- new_covs: cov_u = C - W W^T (or init diag), 25x float4 stream ----
    {
        const float4* C4 = reinterpret_cast<const float4*>(C);
        float4* oc4 = reinterpret_cast<float4*>(out + (size_t)N * 22 + (size_t)n * 100);
        #pragma unroll
        for (int q4 = 0; q4 < 25; q4++) {
            float4 cv = __ldcs(C4 + q4);
            float r[4];
            #pragma unroll
            for (int t = 0; t < 4; t++) {
                int q = q4 * 4 + t;
                int i = q / SD, j = q % SD;
                float c = (t == 0) ? cv.x : (t == 1) ? cv.y : (t == 2) ? cv.z : cv.w;
                float d = 0.0f;
                #pragma unroll
                for (int k = 0; k < MD; k++) d += W[i][k] * W[j][k];
                float cu = c - d;
                float ci = (i == j) ? ((i < MD) ? 10.0f : 10000.0f) : 0.0f;
                r[t] = mt ? cu : ci;
            }
            __stcs(oc4 + q4, make_float4(r[0], r[1], r[2], r[3]));
        }
    }

    // ---- new_boxes_3d ----
    {
        const float4* B4 = reinterpret_cast<const float4*>(boxes + (size_t)n * 12);
        float4 b0 = B4[0], b1 = B4[1], b2 = B4[2];
        float b[12] = {b0.x, b0.y, b0.z, b0.w, b1.x, b1.y, b1.z, b1.w,
                       b2.x, b2.y, b2.z, b2.w};
        float r[12];
        #pragma unroll
        for (int j = 0; j < 6; j++) r[j] = mt ? mu[j] : b[j];
        r[6] = b[6];
        r[7] = b[7];
        r[8] = mt ? mu[6] : b[8];
        #pragma unroll
        for (int j = 0; j < 3; j++) r[9 + j] = mt ? (mu[MD + j] * fps) : b[9 + j];
        float4* ob4 = reinterpret_cast<float4*>(out + (size_t)n * 12);
        ob4[0] = make_float4(r[0], r[1], r[2], r[3]);
        ob4[1] = make_float4(r[4], r[5], r[6], r[7]);
        ob4[2] = make_float4(r[8], r[9], r[10], r[11]);
    }

    // ---- velocities + acc_frames ----
    {
        float gap = (float)frame_gap[n];
        float acc = (float)acc_frames[n];
        const float* pb = prev_b7 + (size_t)n * MD;
        const float* pv = prev_vel + (size_t)n * MD;
        float* ov = out + (size_t)N * 122 + (size_t)n * MD;
        float inv_gap = 1.0f / gap;
        float inv_acc1 = 1.0f / (acc + 1.0f);
        #pragma unroll
        for (int k = 0; k < MD; k++) {
            float vobs = (mu[k] - pb[k]) * inv_gap;
            float vm = (pv[k] * acc + vobs) * inv_acc1;
            ov[k] = mt ? vm : 0.0f;
        }
        out[(size_t)N * 385 + n] = mt ? (acc + 1.0f) : 0.0f;
    }
}

// Embedding EMA: 64 threads per track (float4), warp-uniform matched branch
// so unmatched tracks never touch prev_embeddings. Streaming hints: no reuse.
__global__ __launch_bounds__(256)
void emb_kernel(const float4* __restrict__ prev_emb,
                const float4* __restrict__ emb,
                const int* __restrict__ matched,
                float4* __restrict__ out, int total4)
{
    int idx = blockIdx.x * blockDim.x + threadIdx.x;
    if (idx >= total4) return;
    bool mt = matched[idx >> 6] != 0;
    float4 ev = __ldcs(emb + idx);
    float4 r;
    if (mt) {
        float4 pv = __ldcs(prev_emb + idx);
        r.x = 0.2f * pv.x + 0.8f * ev.x;
        r.y = 0.2f * pv.y + 0.8f * ev.y;
        r.z = 0.2f * pv.z + 0.8f * ev.z;
        r.w = 0.2f * pv.w + 0.8f * ev.w;
    } else {
        r = ev;
    }
    __stcs(out + idx, r);
}

extern "C" void kernel_launch(void* const* d_in, const int* in_sizes, int n_in,
                              void* d_out, int out_size)
{
    const float* boxes   = (const float*)d_in[0];
    const float* obs     = (const float*)d_in[1];
    const float* prev_b7 = (const float*)d_in[2];
    const float* prev_m  = (const float*)d_in[3];
    const float* prev_c  = (const float*)d_in[4];
    const float* prev_v  = (const float*)d_in[5];
    const float* prev_e  = (const float*)d_in[6];
    const float* emb     = (const float*)d_in[7];
    const int*   acc     = (const int*)d_in[8];
    const int*   gap     = (const int*)d_in[9];
    const int*   matched = (const int*)d_in[10];
    const int*   fps     = (const int*)d_in[11];
    float* out = (float*)d_out;

    int N = in_sizes[8];  // acc_frames element count == N

    // emb FIRST: with ncu -s 5 -c 1, the captured 6th launch is then kf_kernel,
    // which has never been profiled. Total time is order-independent.
    int total4 = N * 64;  // N*256 floats / 4
    int threadsB = 256;
    int blocksB = (total4 + threadsB - 1) / threadsB;
    emb_kernel<<<blocksB, threadsB>>>((const float4*)prev_e, (const float4*)emb,
                                      matched,
                                      (float4*)(out + (size_t)N * 129), total4);

    int threadsA = 128;
    int blocksA = (N + threadsA - 1) / threadsA;
    kf_kernel<<<blocksA, threadsA>>>(boxes, obs, prev_b7, prev_m, prev_c, prev_v,
                                     acc, gap, matched, fps, out, N);
}

// round 13
// speedup vs baseline: 2.6246x; 1.4258x over previous
#include <cuda_runtime.h>
#include <cstdint>

// CC3DTrack: per-track Kalman update + embedding EMA.
// kf_kernel exploits bitwise symmetry of prev_covs (A A^T + I) to load only
// the 7x7 lower triangle + rows 7..9 (float2-vectorized), cutting per-thread
// load requests from ~123 to ~53. No streaming hints on cov reads (the row is
// re-read by the float4 cov pass and must stay L1-resident).
//
// Output (concatenated f32): boxes(12N) | means(10N) | covs(100N) | vel(7N) | emb(256N) | acc(1N)

#define MD 7
#define SD 10

__global__ __launch_bounds__(128)
void kf_kernel(const float* __restrict__ boxes,
               const float* __restrict__ obs,
               const float* __restrict__ prev_b7,
               const float* __restrict__ prev_mean,
               const float* __restrict__ prev_cov,
               const float* __restrict__ prev_vel,
               const int*   __restrict__ acc_frames,
               const int*   __restrict__ frame_gap,
               const int*   __restrict__ matched,
               const int*   __restrict__ fps_p,
               float* __restrict__ out, int N)
{
    int n = blockIdx.x * blockDim.x + threadIdx.x;
    if (n >= N) return;

    // fps may be serialized as int32 or float32; sniff the bits.
    int fbits = fps_p[0];
    float fps = ((unsigned)fbits < 1000000u) ? (float)fbits : __int_as_float(fbits);

    const float* C = prev_cov + (size_t)n * 100;
    const bool mt = matched[n] != 0;

    // ---- load lower triangle of C[0:7,0:7] via float2 (8B-aligned: offsets
    //      are n*400 + i*40 + col*4 with col even) ----
    float tri[MD][MD];   // only [i][j], j<=i valid
    #pragma unroll
    for (int i = 0; i < MD; i++) {
        #pragma unroll
        for (int j2 = 0; j2 <= i / 2; j2++) {
            float2 v = *reinterpret_cast<const float2*>(C + i * SD + 2 * j2);
            tri[i][2 * j2] = v.x;
            if (2 * j2 + 1 <= i) tri[i][2 * j2 + 1] = v.y;  // compile-time pred
        }
    }
    // symmetric accessor: C[i][j] for i,j < 7 (bitwise-exact by construction)
    #define CSYM(i, j) ((j) <= (i) ? tri[(i)][(j)] : tri[(j)][(i)])

    // ---- rows 7..9, cols 0..6 (load cols 0..7, 4x float2 per row) ----
    float q[3][8];
    #pragma unroll
    for (int r = 0; r < 3; r++) {
        #pragma unroll
        for (int j2 = 0; j2 < 4; j2++) {
            float2 v = *reinterpret_cast<const float2*>(C + (MD + r) * SD + 2 * j2);
            q[r][2 * j2] = v.x;
            q[r][2 * j2 + 1] = v.y;
        }
    }

    // ---- Cholesky of S = C[0:7,0:7] + I (SPD by construction) ----
    float L[MD][MD];
    float dinv[MD];
    #pragma unroll
    for (int i = 0; i < MD; i++) {
        #pragma unroll
        for (int j = 0; j <= i; j++) {
            float s = tri[i][j] + (i == j ? 1.0f : 0.0f);
            #pragma unroll
            for (int k = 0; k < j; k++) s -= L[i][k] * L[j][k];
            if (j == i) {
                float d = sqrtf(s);
                L[i][i] = d;
                dinv[i] = 1.0f / d;
            } else {
                L[i][j] = s * dinv[j];
            }
        }
    }

    // ---- W[j][:] = L^{-1} * C[j,0:7]^T ----
    // rows 0..6 come from the triangle by symmetry (no loads); rows 7..9 from q.
    float W[SD][MD];
    #pragma unroll
    for (int j = 0; j < SD; j++) {
        float p[MD];
        #pragma unroll
        for (int k = 0; k < MD; k++) p[k] = (j < MD) ? CSYM(j, k) : q[j - MD][k];
        #pragma unroll
        for (int k = 0; k < MD; k++) {
            float s = p[k];
            #pragma unroll
            for (int m = 0; m < k; m++) s -= L[k][m] * W[j][m];
            W[j][k] = s * dinv[k];
        }
    }
    #undef CSYM

    // ---- mean update ----
    float m[SD], o7[MD];
    {
        const float* pm = prev_mean + (size_t)n * SD;  // 8B aligned -> float2
        #pragma unroll
        for (int j2 = 0; j2 < 5; j2++) {
            float2 v = *reinterpret_cast<const float2*>(pm + 2 * j2);
            m[2 * j2] = v.x; m[2 * j2 + 1] = v.y;
        }
        const float* po = obs + (size_t)n * MD;
        #pragma unroll
        for (int k = 0; k < MD; k++) o7[k] = po[k];
    }
    float u[MD];
    #pragma unroll
    for (int k = 0; k < MD; k++) {
        float s = o7[k] - m[k];
        #pragma unroll
        for (int mm = 0; mm < k; mm++) s -= L[k][mm] * u[mm];
        u[k] = s * dinv[k];
    }
    float mu[SD];
    #pragma unroll
    for (int j = 0; j < SD; j++) {
        float d = 0.0f;
        #pragma unroll
        for (int k = 0; k < MD; k++) d += W[j][k] * u[k];
        mu[j] = m[j] + d;
    }

    // ---- new_means ----
    {
        float* om = out + (size_t)N * 12 + (size_t)n * SD;
        float r[SD];
        #pragma unroll
        for (int j = 0; j < MD; j++) r[j] = mt ? mu[j] : o7[j];
        #pragma unroll
        for (int j = MD; j < SD; j++) r[j] = mt ? mu[j] : 0.0f;
        float2* om2 = reinterpret_cast<float2*>(om);
        #pragma unroll
        for (int q2 = 0; q2 < 5; q2++) om2[q2] = make_float2(r[2 * q2], r[2 * q2 + 1]);
    }

    // ---- new_covs: cov_u = C - W W^T (or init diag), 25x float4 stream.
    //      Top rows hit L1 (already touched by the triangle/q loads). ----
    {
        const float4* C4 = reinterpret_cast<const float4*>(C);
        float4* oc4 = reinterpret_cast<float4*>(out + (size_t)N * 22 + (size_t)n * 100);
        #pragma unroll
        for (int q4 = 0; q4 < 25; q4++) {
            float4 cv = C4[q4];
            float r[4];
            #pragma unroll
            for (int t = 0; t < 4; t++) {
                int qq = q4 * 4 + t;
                int i = qq / SD, j = qq % SD;
                float c = (t == 0) ? cv.x : (t == 1) ? cv.y : (t == 2) ? cv.z : cv.w;
                float d = 0.0f;
                #pragma unroll
                for (int k = 0; k < MD; k++) d += W[i][k] * W[j][k];
                float cu = c - d;
                float ci = (i == j) ? ((i < MD) ? 10.0f : 10000.0f) : 0.0f;
                r[t] = mt ? cu : ci;
            }
            oc4[q4] = make_float4(r[0], r[1], r[2], r[3]);
        }
    }

    // ---- new_boxes_3d ----
    {
        const float4* B4 = reinterpret_cast<const float4*>(boxes + (size_t)n * 12);
        float4 b0 = B4[0], b1 = B4[1], b2 = B4[2];
        float b[12] = {b0.x, b0.y, b0.z, b0.w, b1.x, b1.y, b1.z, b1.w,
                       b2.x, b2.y, b2.z, b2.w};
        float r[12];
        #pragma unroll
        for (int j = 0; j < 6; j++) r[j] = mt ? mu[j] : b[j];
        r[6] = b[6];
        r[7] = b[7];
        r[8] = mt ? mu[6] : b[8];
        #pragma unroll
        for (int j = 0; j < 3; j++) r[9 + j] = mt ? (mu[MD + j] * fps) : b[9 + j];
        float4* ob4 = reinterpret_cast<float4*>(out + (size_t)n * 12);
        ob4[0] = make_float4(r[0], r[1], r[2], r[3]);
        ob4[1] = make_float4(r[4], r[5], r[6], r[7]);
        ob4[2] = make_float4(r[8], r[9], r[10], r[11]);
    }

    // ---- velocities + acc_frames ----
    {
        float gap = (float)frame_gap[n];
        float acc = (float)acc_frames[n];
        const float* pb = prev_b7 + (size_t)n * MD;
        const float* pv = prev_vel + (size_t)n * MD;
        float* ov = out + (size_t)N * 122 + (size_t)n * MD;
        float inv_gap = 1.0f / gap;
        float inv_acc1 = 1.0f / (acc + 1.0f);
        #pragma unroll
        for (int k = 0; k < MD; k++) {
            float vobs = (mu[k] - pb[k]) * inv_gap;
            float vm = (pv[k] * acc + vobs) * inv_acc1;
            ov[k] = mt ? vm : 0.0f;
        }
        out[(size_t)N * 385 + n] = mt ? (acc + 1.0f) : 0.0f;
    }
}

// Embedding EMA: 64 threads per track (float4), warp-uniform matched branch
// so unmatched tracks never touch prev_embeddings. Streaming hints: no reuse.
__global__ __launch_bounds__(256)
void emb_kernel(const float4* __restrict__ prev_emb,
                const float4* __restrict__ emb,
                const int* __restrict__ matched,
                float4* __restrict__ out, int total4)
{
    int idx = blockIdx.x * blockDim.x + threadIdx.x;
    if (idx >= total4) return;
    bool mt = matched[idx >> 6] != 0;
    float4 ev = __ldcs(emb + idx);
    float4 r;
    if (mt) {
        float4 pv = __ldcs(prev_emb + idx);
        r.x = 0.2f * pv.x + 0.8f * ev.x;
        r.y = 0.2f * pv.y + 0.8f * ev.y;
        r.z = 0.2f * pv.z + 0.8f * ev.z;
        r.w = 0.2f * pv.w + 0.8f * ev.w;
    } else {
        r = ev;
    }
    __stcs(out + idx, r);
}

extern "C" void kernel_launch(void* const* d_in, const int* in_sizes, int n_in,
                              void* d_out, int out_size)
{
    const float* boxes   = (const float*)d_in[0];
    const float* obs     = (const float*)d_in[1];
    const float* prev_b7 = (const float*)d_in[2];
    const float* prev_m  = (const float*)d_in[3];
    const float* prev_c  = (const float*)d_in[4];
    const float* prev_v  = (const float*)d_in[5];
    const float* prev_e  = (const float*)d_in[6];
    const float* emb     = (const float*)d_in[7];
    const int*   acc     = (const int*)d_in[8];
    const int*   gap     = (const int*)d_in[9];
    const int*   matched = (const int*)d_in[10];
    const int*   fps     = (const int*)d_in[11];
    float* out = (float*)d_out;

    int N = in_sizes[8];  // acc_frames element count == N

    // emb FIRST so the ncu capture window (-s 5 -c 1) stays on kf_kernel.
    int total4 = N * 64;  // N*256 floats / 4
    int threadsB = 256;
    int blocksB = (total4 + threadsB - 1) / threadsB;
    emb_kernel<<<blocksB, threadsB>>>((const float4*)prev_e, (const float4*)emb,
                                      matched,
                                      (float4*)(out + (size_t)N * 129), total4);

    int threadsA = 128;
    int blocksA = (N + threadsA - 1) / threadsA;
    kf_kernel<<<blocksA, threadsA>>>(boxes, obs, prev_b7, prev_m, prev_c, prev_v,
                                     acc, gap, matched, fps, out, N);
}